// round 15
// baseline (speedup 1.0000x reference)
#include <cuda_runtime.h>
#include <cuda_bf16.h>

// Problem constants
#define BATCH 32
#define CH    256
#define HH    64
#define WW    64
#define HW    (HH*WW)            // 4096
#define HW4   (HW/4)             // 1024 float4 per image plane
#define EPSV  1e-5f

#define CHUNKS   8               // channel chunks per block (pool)
#define CPC      (CH/CHUNKS)     // 32 channels per chunk
#define PIX      32              // float4 pixels per block (pool)

#define MPLANES  2               // planes per mul CTA (4096 blocks)

// Scratch (allocation-free rule: __device__ globals)
__device__ float g_pooled[BATCH * 2 * HW];   // [B, {max,mean}, H, W]
__device__ float g_att[BATCH * HW];          // [B, H, W]

__device__ __forceinline__ float4 ldcs4(const float4* p) {
    return __ldcs(p);
}

// ---------------------------------------------------------------------------
// Kernel 1: channel pooling (max + mean over C) -> g_pooled.
// Block = 256 threads = 32 float4-pixels x 8 channel-chunks, grid = 1024.
// x reads are __ldcs (evict-first): the cached copy is provably never
// usefully reused (cross-kernel handoff measured dead), so don't let it
// occupy L2 allocation bandwidth.
// ---------------------------------------------------------------------------
__global__ __launch_bounds__(256) void pool_kernel(const float* __restrict__ x) {
    __shared__ float4 smx[CHUNKS * PIX];
    __shared__ float4 ssm[CHUNKS * PIX];

    int tid   = threadIdx.x;
    int pix   = tid & (PIX - 1);       // 0..31
    int chunk = tid >> 5;              // 0..7

    int blk    = blockIdx.x;           // 0..1023
    int b      = blk >> 5;             // 32 blocks per batch
    int p4base = (blk & 31) * PIX;
    int p4     = p4base + pix;

    const float4* xb = (const float4*)(x + (size_t)b * CH * HW) + p4
                     + (size_t)(chunk * CPC) * HW4;

    float4 v  = ldcs4(xb);
    float4 mx = v;
    float4 sm = v;
#pragma unroll
    for (int c = 1; c < CPC; c++) {
        float4 t = ldcs4(xb + (size_t)c * HW4);
        mx.x = fmaxf(mx.x, t.x); mx.y = fmaxf(mx.y, t.y);
        mx.z = fmaxf(mx.z, t.z); mx.w = fmaxf(mx.w, t.w);
        sm.x += t.x; sm.y += t.y; sm.z += t.z; sm.w += t.w;
    }
    smx[tid] = mx;
    ssm[tid] = sm;
    __syncthreads();

#pragma unroll
    for (int s = 128; s >= PIX; s >>= 1) {
        if (tid < s) {
            float4 am = smx[tid], bm = smx[tid + s];
            am.x = fmaxf(am.x, bm.x); am.y = fmaxf(am.y, bm.y);
            am.z = fmaxf(am.z, bm.z); am.w = fmaxf(am.w, bm.w);
            smx[tid] = am;
            float4 as = ssm[tid], bs = ssm[tid + s];
            as.x += bs.x; as.y += bs.y; as.z += bs.z; as.w += bs.w;
            ssm[tid] = as;
        }
        __syncthreads();
    }

    if (tid < PIX) {
        const float inv = 1.0f / (float)CH;
        float4 mxr = smx[tid];
        float4 smr = ssm[tid];
        float4 av = make_float4(smr.x * inv, smr.y * inv, smr.z * inv, smr.w * inv);
        float4* pmax = (float4*)(g_pooled + (size_t)b * 2 * HW) + p4base + tid;
        float4* pavg = (float4*)(g_pooled + (size_t)b * 2 * HW + HW) + p4base + tid;
        *pmax = mxr;
        *pavg = av;
    }
}

// ---------------------------------------------------------------------------
// Kernel 2: 3x (7x7 conv 2->1 + BN + sigmoid), averaged -> g_att  (R1-proven)
// ---------------------------------------------------------------------------
__global__ void att_kernel(const float* __restrict__ w1,
                           const float* __restrict__ g1, const float* __restrict__ b1,
                           const float* __restrict__ m1, const float* __restrict__ v1,
                           const float* __restrict__ w2,
                           const float* __restrict__ g2, const float* __restrict__ b2,
                           const float* __restrict__ m2, const float* __restrict__ v2,
                           const float* __restrict__ w3,
                           const float* __restrict__ g3, const float* __restrict__ b3,
                           const float* __restrict__ m3, const float* __restrict__ v3) {
    __shared__ float ws[3][2][49];   // BN-scaled effective weights
    __shared__ float bias[3];

    int tid = threadIdx.x;

    if (tid < 3) {
        const float* g  = (tid == 0) ? g1 : (tid == 1) ? g2 : g3;
        const float* be = (tid == 0) ? b1 : (tid == 1) ? b2 : b3;
        const float* m  = (tid == 0) ? m1 : (tid == 1) ? m2 : m3;
        const float* v  = (tid == 0) ? v1 : (tid == 1) ? v2 : v3;
        float s = g[0] * rsqrtf(v[0] + EPSV);
        bias[tid] = be[0] - m[0] * s;
    }

    for (int k = tid; k < 3 * 2 * 49; k += blockDim.x) {
        int br = k / 98;
        int r  = k % 98;
        int i  = r / 49;
        int kk = r % 49;
        int kh = kk / 7, kw = kk % 7;
        float s, raw;
        if (br == 0) {
            s = g1[0] * rsqrtf(v1[0] + EPSV);
            raw = w1[i * 49 + kh * 7 + kw];
        } else if (br == 1) {
            s = g2[0] * rsqrtf(v2[0] + EPSV);
            raw = w2[i * 49 + kw * 7 + kh];   // transposed kernel
        } else {
            s = g3[0] * rsqrtf(v3[0] + EPSV);
            raw = w3[i * 49 + kh * 7 + kw];
        }
        ws[br][i][kk] = raw * s;
    }
    __syncthreads();

    int blk = blockIdx.x;
    int b = blk >> 4;                 // / 16
    int row_base = (blk & 15) * 4;
    int h = row_base + (tid >> 6);
    int w = tid & 63;

    const float* pmax = g_pooled + (size_t)b * 2 * HW;
    const float* pavg = pmax + HW;

    float acc0 = 0.f, acc1 = 0.f, acc2 = 0.f;
#pragma unroll
    for (int kh = 0; kh < 7; kh++) {
        int hh = h + kh - 3;
        if (hh < 0 || hh >= HH) continue;
#pragma unroll
        for (int kw = 0; kw < 7; kw++) {
            int wv = w + kw - 3;
            if (wv < 0 || wv >= WW) continue;
            int off = hh * WW + wv;
            float pm = pmax[off];
            float pa = pavg[off];
            int kk = kh * 7 + kw;
            acc0 = fmaf(ws[0][0][kk], pm, acc0);
            acc0 = fmaf(ws[0][1][kk], pa, acc0);
            acc1 = fmaf(ws[1][0][kk], pm, acc1);
            acc1 = fmaf(ws[1][1][kk], pa, acc1);
            acc2 = fmaf(ws[2][0][kk], pm, acc2);
            acc2 = fmaf(ws[2][1][kk], pa, acc2);
        }
    }
    float s0 = 1.0f / (1.0f + __expf(-(acc0 + bias[0])));
    float s1 = 1.0f / (1.0f + __expf(-(acc1 + bias[1])));
    float s2 = 1.0f / (1.0f + __expf(-(acc2 + bias[2])));
    g_att[(size_t)b * HW + h * WW + w] = (s0 + s1 + s2) * (1.0f / 3.0f);
}

// ---------------------------------------------------------------------------
// Kernel 3: out = x * att. 2 planes per CTA (4096 blocks).
// att slice loaded once per CTA (L2-hot), x loads __ldcs front-batched 8
// LDG.128 deep, out stores __stcs. Pure streaming, no L2 allocation churn.
// ---------------------------------------------------------------------------
__global__ __launch_bounds__(256) void mul_kernel(const float* __restrict__ x,
                                                  float* __restrict__ out) {
    int blk = blockIdx.x;              // [0, BATCH*CH/MPLANES)
    int tid = threadIdx.x;
    int b   = blk >> 7;                // 128 blocks per image (256/2 planes)

    size_t plane0 = (size_t)blk * MPLANES;
    const float4* xp = (const float4*)x + plane0 * HW4;
    float4*       op = (float4*)out    + plane0 * HW4;
    const float4* ap = (const float4*)g_att + (size_t)b * HW4;

    // att slice for this thread, reused for both planes
    float4 av[4];
#pragma unroll
    for (int i = 0; i < 4; i++) av[i] = ap[tid + i * 256];

    // Front-batch all 8 x loads (2 planes x 4 f4)
    float4 xv[8];
#pragma unroll
    for (int i = 0; i < 4; i++)
        xv[i]     = ldcs4(xp + tid + i * 256);
#pragma unroll
    for (int i = 0; i < 4; i++)
        xv[4 + i] = ldcs4(xp + HW4 + tid + i * 256);

#pragma unroll
    for (int i = 0; i < 4; i++) {
        float4 o;
        o.x = xv[i].x * av[i].x; o.y = xv[i].y * av[i].y;
        o.z = xv[i].z * av[i].z; o.w = xv[i].w * av[i].w;
        __stcs(op + tid + i * 256, o);
    }
#pragma unroll
    for (int i = 0; i < 4; i++) {
        float4 o;
        o.x = xv[4+i].x * av[i].x; o.y = xv[4+i].y * av[i].y;
        o.z = xv[4+i].z * av[i].z; o.w = xv[4+i].w * av[i].w;
        __stcs(op + HW4 + tid + i * 256, o);
    }
}

extern "C" void kernel_launch(void* const* d_in, const int* in_sizes, int n_in,
                              void* d_out, int out_size) {
    const float* x  = (const float*)d_in[0];
    const float* w1 = (const float*)d_in[1];
    const float* g1 = (const float*)d_in[2];
    const float* b1 = (const float*)d_in[3];
    const float* m1 = (const float*)d_in[4];
    const float* v1 = (const float*)d_in[5];
    const float* w2 = (const float*)d_in[6];
    const float* g2 = (const float*)d_in[7];
    const float* b2 = (const float*)d_in[8];
    const float* m2 = (const float*)d_in[9];
    const float* v2 = (const float*)d_in[10];
    const float* w3 = (const float*)d_in[11];
    const float* g3 = (const float*)d_in[12];
    const float* b3 = (const float*)d_in[13];
    const float* m3 = (const float*)d_in[14];
    const float* v3 = (const float*)d_in[15];
    float* out = (float*)d_out;

    // K1: pooling  (1024 blocks)
    pool_kernel<<<BATCH * HW4 / PIX, 256>>>(x);

    // K2: attention map
    att_kernel<<<BATCH * (HH / 4), 256>>>(w1, g1, b1, m1, v1,
                                          w2, g2, b2, m2, v2,
                                          w3, g3, b3, m3, v3);

    // K3: elementwise multiply, 2 planes per CTA (4096 blocks)
    mul_kernel<<<BATCH * CH / MPLANES, 256>>>(x, out);
}

// round 16
// speedup vs baseline: 1.0334x; 1.0334x over previous
#include <cuda_runtime.h>
#include <cuda_bf16.h>

// Problem constants
#define BATCH 32
#define CH    256
#define HH    64
#define WW    64
#define HW    (HH*WW)            // 4096
#define HW4   (HW/4)             // 1024 float4 per image plane
#define EPSV  1e-5f

#define CHUNKS   8               // channel chunks per block (pool)
#define CPC      (CH/CHUNKS)     // 32 channels per chunk
#define PIX      32              // float4 pixels per block (pool)

// Scratch (allocation-free rule: __device__ globals)
__device__ float g_pooled[BATCH * 2 * HW];   // [B, {max,mean}, H, W]
__device__ float g_att[BATCH * HW];          // [B, H, W]

// ---------------------------------------------------------------------------
// Kernel 1: channel pooling (max + mean over C) -> g_pooled  (measured best)
// Block = 256 threads = 32 float4-pixels x 8 channel-chunks, grid = 1024.
// Default load policy (measured faster than __ldcs by ~2.4us).
// ---------------------------------------------------------------------------
__global__ __launch_bounds__(256) void pool_kernel(const float* __restrict__ x) {
    __shared__ float4 smx[CHUNKS * PIX];
    __shared__ float4 ssm[CHUNKS * PIX];

    int tid   = threadIdx.x;
    int pix   = tid & (PIX - 1);       // 0..31
    int chunk = tid >> 5;              // 0..7

    int blk    = blockIdx.x;           // 0..1023
    int b      = blk >> 5;             // 32 blocks per batch
    int p4base = (blk & 31) * PIX;
    int p4     = p4base + pix;

    const float4* xb = (const float4*)(x + (size_t)b * CH * HW) + p4
                     + (size_t)(chunk * CPC) * HW4;

    float4 v  = xb[0];
    float4 mx = v;
    float4 sm = v;
#pragma unroll
    for (int c = 1; c < CPC; c++) {
        float4 t = xb[(size_t)c * HW4];
        mx.x = fmaxf(mx.x, t.x); mx.y = fmaxf(mx.y, t.y);
        mx.z = fmaxf(mx.z, t.z); mx.w = fmaxf(mx.w, t.w);
        sm.x += t.x; sm.y += t.y; sm.z += t.z; sm.w += t.w;
    }
    smx[tid] = mx;
    ssm[tid] = sm;
    __syncthreads();

#pragma unroll
    for (int s = 128; s >= PIX; s >>= 1) {
        if (tid < s) {
            float4 am = smx[tid], bm = smx[tid + s];
            am.x = fmaxf(am.x, bm.x); am.y = fmaxf(am.y, bm.y);
            am.z = fmaxf(am.z, bm.z); am.w = fmaxf(am.w, bm.w);
            smx[tid] = am;
            float4 as = ssm[tid], bs = ssm[tid + s];
            as.x += bs.x; as.y += bs.y; as.z += bs.z; as.w += bs.w;
            ssm[tid] = as;
        }
        __syncthreads();
    }

    if (tid < PIX) {
        const float inv = 1.0f / (float)CH;
        float4 mxr = smx[tid];
        float4 smr = ssm[tid];
        float4 av = make_float4(smr.x * inv, smr.y * inv, smr.z * inv, smr.w * inv);
        float4* pmax = (float4*)(g_pooled + (size_t)b * 2 * HW) + p4base + tid;
        float4* pavg = (float4*)(g_pooled + (size_t)b * 2 * HW + HW) + p4base + tid;
        *pmax = mxr;
        *pavg = av;
    }
}

// ---------------------------------------------------------------------------
// Kernel 2: 3x (7x7 conv 2->1 + BN + sigmoid), averaged -> g_att
// Branch 2 = conv with kh<->kw transposed kernel. BN folded.
// ---------------------------------------------------------------------------
__global__ void att_kernel(const float* __restrict__ w1,
                           const float* __restrict__ g1, const float* __restrict__ b1,
                           const float* __restrict__ m1, const float* __restrict__ v1,
                           const float* __restrict__ w2,
                           const float* __restrict__ g2, const float* __restrict__ b2,
                           const float* __restrict__ m2, const float* __restrict__ v2,
                           const float* __restrict__ w3,
                           const float* __restrict__ g3, const float* __restrict__ b3,
                           const float* __restrict__ m3, const float* __restrict__ v3) {
    __shared__ float ws[3][2][49];   // BN-scaled effective weights
    __shared__ float bias[3];

    int tid = threadIdx.x;

    if (tid < 3) {
        const float* g  = (tid == 0) ? g1 : (tid == 1) ? g2 : g3;
        const float* be = (tid == 0) ? b1 : (tid == 1) ? b2 : b3;
        const float* m  = (tid == 0) ? m1 : (tid == 1) ? m2 : m3;
        const float* v  = (tid == 0) ? v1 : (tid == 1) ? v2 : v3;
        float s = g[0] * rsqrtf(v[0] + EPSV);
        bias[tid] = be[0] - m[0] * s;
    }

    for (int k = tid; k < 3 * 2 * 49; k += blockDim.x) {
        int br = k / 98;
        int r  = k % 98;
        int i  = r / 49;
        int kk = r % 49;
        int kh = kk / 7, kw = kk % 7;
        float s, raw;
        if (br == 0) {
            s = g1[0] * rsqrtf(v1[0] + EPSV);
            raw = w1[i * 49 + kh * 7 + kw];
        } else if (br == 1) {
            s = g2[0] * rsqrtf(v2[0] + EPSV);
            raw = w2[i * 49 + kw * 7 + kh];   // transposed kernel
        } else {
            s = g3[0] * rsqrtf(v3[0] + EPSV);
            raw = w3[i * 49 + kh * 7 + kw];
        }
        ws[br][i][kk] = raw * s;
    }
    __syncthreads();

    int blk = blockIdx.x;
    int b = blk >> 4;                 // / 16
    int row_base = (blk & 15) * 4;
    int h = row_base + (tid >> 6);
    int w = tid & 63;

    const float* pmax = g_pooled + (size_t)b * 2 * HW;
    const float* pavg = pmax + HW;

    float acc0 = 0.f, acc1 = 0.f, acc2 = 0.f;
#pragma unroll
    for (int kh = 0; kh < 7; kh++) {
        int hh = h + kh - 3;
        if (hh < 0 || hh >= HH) continue;
#pragma unroll
        for (int kw = 0; kw < 7; kw++) {
            int wv = w + kw - 3;
            if (wv < 0 || wv >= WW) continue;
            int off = hh * WW + wv;
            float pm = pmax[off];
            float pa = pavg[off];
            int kk = kh * 7 + kw;
            acc0 = fmaf(ws[0][0][kk], pm, acc0);
            acc0 = fmaf(ws[0][1][kk], pa, acc0);
            acc1 = fmaf(ws[1][0][kk], pm, acc1);
            acc1 = fmaf(ws[1][1][kk], pa, acc1);
            acc2 = fmaf(ws[2][0][kk], pm, acc2);
            acc2 = fmaf(ws[2][1][kk], pa, acc2);
        }
    }
    float s0 = 1.0f / (1.0f + __expf(-(acc0 + bias[0])));
    float s1 = 1.0f / (1.0f + __expf(-(acc1 + bias[1])));
    float s2 = 1.0f / (1.0f + __expf(-(acc2 + bias[2])));
    g_att[(size_t)b * HW + h * WW + w] = (s0 + s1 + s2) * (1.0f / 3.0f);
}

// ---------------------------------------------------------------------------
// Kernel 3: out = x * att, ILP=4, reversed plane order (measured best).
// One block per (image, channel) plane; 4 float4 per thread, front-batched
// loads; __stcs stores.
// ---------------------------------------------------------------------------
__global__ __launch_bounds__(256) void mul_kernel(const float* __restrict__ x,
                                                  float* __restrict__ out) {
    int blk = (BATCH * CH - 1) - blockIdx.x;   // reversed plane index: b*CH + c
    int tid = threadIdx.x;
    int b   = blk >> 8;

    const float4* xp = (const float4*)x + (size_t)blk * HW4;
    float4*       op = (float4*)out    + (size_t)blk * HW4;
    const float4* ap = (const float4*)g_att + (size_t)b * HW4;

    float4 xv[4], av[4];
#pragma unroll
    for (int i = 0; i < 4; i++) xv[i] = xp[tid + i * 256];
#pragma unroll
    for (int i = 0; i < 4; i++) av[i] = ap[tid + i * 256];
#pragma unroll
    for (int i = 0; i < 4; i++) {
        float4 o;
        o.x = xv[i].x * av[i].x; o.y = xv[i].y * av[i].y;
        o.z = xv[i].z * av[i].z; o.w = xv[i].w * av[i].w;
        __stcs(op + tid + i * 256, o);
    }
}

extern "C" void kernel_launch(void* const* d_in, const int* in_sizes, int n_in,
                              void* d_out, int out_size) {
    const float* x  = (const float*)d_in[0];
    const float* w1 = (const float*)d_in[1];
    const float* g1 = (const float*)d_in[2];
    const float* b1 = (const float*)d_in[3];
    const float* m1 = (const float*)d_in[4];
    const float* v1 = (const float*)d_in[5];
    const float* w2 = (const float*)d_in[6];
    const float* g2 = (const float*)d_in[7];
    const float* b2 = (const float*)d_in[8];
    const float* m2 = (const float*)d_in[9];
    const float* v2 = (const float*)d_in[10];
    const float* w3 = (const float*)d_in[11];
    const float* g3 = (const float*)d_in[12];
    const float* b3 = (const float*)d_in[13];
    const float* m3 = (const float*)d_in[14];
    const float* v3 = (const float*)d_in[15];
    float* out = (float*)d_out;

    // K1: pooling  (1024 blocks)
    pool_kernel<<<BATCH * HW4 / PIX, 256>>>(x);

    // K2: attention map
    att_kernel<<<BATCH * (HH / 4), 256>>>(w1, g1, b1, m1, v1,
                                          w2, g2, b2, m2, v2,
                                          w3, g3, b3, m3, v3);

    // K3: elementwise multiply, one block per (b, c) plane, reversed order
    mul_kernel<<<BATCH * CH, 256>>>(x, out);
}